// round 1
// baseline (speedup 1.0000x reference)
#include <cuda_runtime.h>
#include <math.h>

#define NN 170
#define TT 12
#define BB 32
#define DD 120
#define HH 8
#define HD 15
#define FF 2048
#define BT (BB*TT)          // 384
#define MTOK (BB*TT*NN)     // 65280

#define FLAG_ACCUM 1
#define FLAG_BIAS  2
#define FLAG_RELU  4

// ------------------------- static device scratch -------------------------
__device__ float g_L[3*NN*NN];
__device__ float g_A[3*NN*NN];
__device__ float g_rs0[3*NN];
__device__ float g_rs1[3*NN];
__device__ float g_tmp1[(size_t)BT*NN*DD];
__device__ float g_tmp2[(size_t)BT*NN*DD];
__device__ float g_q[(size_t)BT*NN*DD];
__device__ float g_k[(size_t)BT*NN*DD];
__device__ float g_v[(size_t)BT*NN*DD];
__device__ float g_oattn[(size_t)BT*NN*DD];
__device__ float g_oproj[(size_t)BT*NN*DD];
__device__ float g_out1[(size_t)BT*NN*DD];
__device__ float g_hidden[(size_t)MTOK*FF];

// ------------------------- graph learning kernels -------------------------
// Stage 1: new = relu(w1 w2^T - w2 w1^T + diag(beta)); gate mix with adj.
// Writes g_A and row sums to g_rs0.
__global__ void gk1(const float* __restrict__ w1, const float* __restrict__ w2,
                    const float* __restrict__ beta, const float* __restrict__ cw,
                    const float* __restrict__ cb, const float* __restrict__ adj) {
    int r = blockIdx.x, br = blockIdx.y;
    __shared__ float w1r[DD], w2r[DD];
    __shared__ float red[256];
    const float* W1 = w1 + (size_t)br*NN*DD;
    const float* W2 = w2 + (size_t)br*NN*DD;
    for (int i = threadIdx.x; i < DD; i += blockDim.x) {
        w1r[i] = W1[r*DD + i];
        w2r[i] = W2[r*DD + i];
    }
    __syncthreads();
    float cw0 = cw[br*2+0], cw1 = cw[br*2+1], cbv = cb[br];
    float mysum = 0.f;
    for (int c = threadIdx.x; c < NN; c += blockDim.x) {
        const float* w1c = W1 + c*DD;
        const float* w2c = W2 + c*DD;
        float d1 = 0.f, d2 = 0.f;
        for (int e = 0; e < DD; e++) {
            d1 += w1r[e] * w2c[e];
            d2 += w2r[e] * w1c[e];
        }
        float nw = d1 - d2;
        if (r == c) nw += beta[br*NN + r];
        nw = fmaxf(nw, 0.f);
        float ad = adj[r*NN + c];
        float z = cw0*nw + cw1*ad + cbv;
        float gate = 1.f / (1.f + expf(-z));
        float a = gate*nw + (1.f - gate)*ad;
        g_A[(size_t)br*NN*NN + (size_t)r*NN + c] = a;
        mysum += a;
    }
    red[threadIdx.x] = mysum;
    __syncthreads();
    for (int s = 128; s > 0; s >>= 1) {
        if (threadIdx.x < s) red[threadIdx.x] += red[threadIdx.x + s];
        __syncthreads();
    }
    if (threadIdx.x == 0) g_rs0[br*NN + r] = red[0];
}

// Stage 2: a = relu(d_r * a * d_c - eps), d=rsqrt(rs0); rowsums -> rs1
__global__ void gk2() {
    int r = blockIdx.x, br = blockIdx.y;
    __shared__ float red[256];
    float dr = rsqrtf(g_rs0[br*NN + r]);
    const float eps = 0.5f / (float)NN;
    float mysum = 0.f;
    for (int c = threadIdx.x; c < NN; c += blockDim.x) {
        float dc = rsqrtf(g_rs0[br*NN + c]);
        size_t idx = (size_t)br*NN*NN + (size_t)r*NN + c;
        float a = fmaxf(dr * g_A[idx] * dc - eps, 0.f);
        g_A[idx] = a;
        mysum += a;
    }
    red[threadIdx.x] = mysum;
    __syncthreads();
    for (int s = 128; s > 0; s >>= 1) {
        if (threadIdx.x < s) red[threadIdx.x] += red[threadIdx.x + s];
        __syncthreads();
    }
    if (threadIdx.x == 0) g_rs1[br*NN + r] = red[0];
}

// Stage 3: g = d_r * a * d_c, d=rsqrt(rs1); rowsums -> rs0
__global__ void gk3() {
    int r = blockIdx.x, br = blockIdx.y;
    __shared__ float red[256];
    float dr = rsqrtf(g_rs1[br*NN + r]);
    float mysum = 0.f;
    for (int c = threadIdx.x; c < NN; c += blockDim.x) {
        float dc = rsqrtf(g_rs1[br*NN + c]);
        size_t idx = (size_t)br*NN*NN + (size_t)r*NN + c;
        float g = dr * g_A[idx] * dc;
        g_A[idx] = g;
        mysum += g;
    }
    red[threadIdx.x] = mysum;
    __syncthreads();
    for (int s = 128; s > 0; s >>= 1) {
        if (threadIdx.x < s) red[threadIdx.x] += red[threadIdx.x + s];
        __syncthreads();
    }
    if (threadIdx.x == 0) g_rs0[br*NN + r] = red[0];
}

// Stage 4: L = I - e_r * g * e_c, e = rsqrt(rs0)
__global__ void gk4() {
    int r = blockIdx.x, br = blockIdx.y;
    float er = rsqrtf(g_rs0[br*NN + r]);
    for (int c = threadIdx.x; c < NN; c += blockDim.x) {
        float ec = rsqrtf(g_rs0[br*NN + c]);
        size_t idx = (size_t)br*NN*NN + (size_t)r*NN + c;
        float L = ((r == c) ? 1.f : 0.f) - er * g_A[idx] * ec;
        g_L[idx] = L;
    }
}

// ------------------------- generic fused SGEMM -------------------------
// C = alpha*(A@B) [+ C if ACCUM] [+ gamma*E] [+ bias] [relu]
// A: MxK row-major, B: KxN row-major, batched via blockIdx.z with strides.
__global__ void sgemm(const float* __restrict__ A, const float* __restrict__ B,
                      float* __restrict__ C, const float* __restrict__ E,
                      const float* __restrict__ bias,
                      int M, int N, int K, float alpha, float gamma, int flags,
                      long sA, long sB, long sC, long sE) {
    A += (long)blockIdx.z * sA;
    B += (long)blockIdx.z * sB;
    C += (long)blockIdx.z * sC;
    if (E) E += (long)blockIdx.z * sE;

    __shared__ float As[8][64];
    __shared__ float Bs[8][64];
    int tid = threadIdx.x;
    int tx = tid & 15, ty = tid >> 4;
    int row0 = blockIdx.y * 64, col0 = blockIdx.x * 64;

    float acc[4][4] = {};

    for (int k0 = 0; k0 < K; k0 += 8) {
        #pragma unroll
        for (int i = tid; i < 512; i += 256) {
            int rr = i >> 3, kk = i & 7;
            int gr = row0 + rr, gk = k0 + kk;
            As[kk][rr] = (gr < M && gk < K) ? A[(long)gr*K + gk] : 0.f;
        }
        #pragma unroll
        for (int i = tid; i < 512; i += 256) {
            int kk = i >> 6, cc = i & 63;
            int gk = k0 + kk, gc = col0 + cc;
            Bs[kk][cc] = (gk < K && gc < N) ? B[(long)gk*N + gc] : 0.f;
        }
        __syncthreads();
        #pragma unroll
        for (int kk = 0; kk < 8; kk++) {
            float a[4], b[4];
            #pragma unroll
            for (int i = 0; i < 4; i++) a[i] = As[kk][ty*4 + i];
            #pragma unroll
            for (int j = 0; j < 4; j++) b[j] = Bs[kk][tx*4 + j];
            #pragma unroll
            for (int i = 0; i < 4; i++)
                #pragma unroll
                for (int j = 0; j < 4; j++)
                    acc[i][j] += a[i] * b[j];
        }
        __syncthreads();
    }

    #pragma unroll
    for (int i = 0; i < 4; i++) {
        #pragma unroll
        for (int j = 0; j < 4; j++) {
            int gr = row0 + ty*4 + i, gc = col0 + tx*4 + j;
            if (gr < M && gc < N) {
                long idx = (long)gr*N + gc;
                float v = alpha * acc[i][j];
                if (flags & FLAG_ACCUM) v += C[idx];
                if (E) v += gamma * E[idx];
                if (flags & FLAG_BIAS) v += bias[gc];
                if (flags & FLAG_RELU) v = fmaxf(v, 0.f);
                C[idx] = v;
            }
        }
    }
}

// ------------------------- attention -------------------------
// One block per (b, n). q,k,v layout (B,T,N,D). Output o layout (B,N,T,D).
__global__ void attn_kernel(const float* __restrict__ q, const float* __restrict__ k,
                            const float* __restrict__ v, float* __restrict__ o) {
    int bn = blockIdx.x;
    int b = bn / NN, n = bn % NN;
    __shared__ float qs[TT][DD], ks[TT][DD], vs[TT][DD];
    for (int i = threadIdx.x; i < TT*DD; i += blockDim.x) {
        int t = i / DD, d = i % DD;
        size_t gi = ((((size_t)b*TT + t)*NN) + n)*DD + d;
        qs[t][d] = q[gi];
        ks[t][d] = k[gi];
        vs[t][d] = v[gi];
    }
    __syncthreads();
    int tid = threadIdx.x;
    if (tid < HH*TT) {
        int h = tid / TT, qi = tid % TT;
        const float scale = rsqrtf((float)HD);
        float s[TT];
        float mx = -1e30f;
        #pragma unroll
        for (int j = 0; j < TT; j++) {
            float acc = 0.f;
            #pragma unroll
            for (int e = 0; e < HD; e++) acc += qs[qi][h*HD + e] * ks[j][h*HD + e];
            acc *= scale;
            s[j] = acc;
            mx = fmaxf(mx, acc);
        }
        float sum = 0.f;
        #pragma unroll
        for (int j = 0; j < TT; j++) { s[j] = expf(s[j] - mx); sum += s[j]; }
        float inv = 1.f / sum;
        size_t obase = ((size_t)bn*TT + qi)*DD + h*HD;
        #pragma unroll
        for (int e = 0; e < HD; e++) {
            float acc = 0.f;
            #pragma unroll
            for (int j = 0; j < TT; j++) acc += s[j] * vs[j][h*HD + e];
            o[obase + e] = acc * inv;
        }
    }
}

// ------------------------- fused residual + layernorm -------------------------
// out[m,:] = LN(xa[m,:] + xb[ib,:]); xb optionally in (B,N,T,D) layout.
__global__ void ln_kernel(const float* __restrict__ xa, const float* __restrict__ xb,
                          const float* __restrict__ gg, const float* __restrict__ bb,
                          float* __restrict__ outp, int transpose_b) {
    int warp = threadIdx.x >> 5, lane = threadIdx.x & 31;
    size_t m = (size_t)blockIdx.x * 4 + warp;
    if (m >= MTOK) return;
    int bidx = (int)(m / (TT*NN));
    int rem = (int)(m % (TT*NN));
    int t = rem / NN, n = rem % NN;
    size_t ia = m * DD;
    size_t ib = transpose_b ? ((((size_t)bidx*NN + n)*TT + t)*DD) : ia;

    float v[4];
    float s = 0.f;
    #pragma unroll
    for (int i = 0; i < 4; i++) {
        int d = lane + 32*i;
        float val = (d < DD) ? (xa[ia + d] + xb[ib + d]) : 0.f;
        v[i] = val;
        s += val;
    }
    #pragma unroll
    for (int o = 16; o > 0; o >>= 1) s += __shfl_xor_sync(0xffffffffu, s, o);
    float mean = s * (1.f / DD);
    float vsum = 0.f;
    #pragma unroll
    for (int i = 0; i < 4; i++) {
        int d = lane + 32*i;
        if (d < DD) { float df = v[i] - mean; vsum += df*df; }
    }
    #pragma unroll
    for (int o = 16; o > 0; o >>= 1) vsum += __shfl_xor_sync(0xffffffffu, vsum, o);
    float inv = rsqrtf(vsum * (1.f / DD) + 1e-5f);
    #pragma unroll
    for (int i = 0; i < 4; i++) {
        int d = lane + 32*i;
        if (d < DD) outp[ia + d] = (v[i] - mean) * inv * gg[d] + bb[d];
    }
}

// ------------------------- launch -------------------------
extern "C" void kernel_launch(void* const* d_in, const int* in_sizes, int n_in,
                              void* d_out, int out_size) {
    const float* x       = (const float*)d_in[0];
    const float* adj     = (const float*)d_in[1];
    const float* gl_beta = (const float*)d_in[2];
    const float* gl_w1   = (const float*)d_in[3];
    const float* gl_w2   = (const float*)d_in[4];
    const float* gl_cw   = (const float*)d_in[5];
    const float* gl_cb   = (const float*)d_in[6];
    const float* cheb_w  = (const float*)d_in[7];
    const float* cheb_b  = (const float*)d_in[8];
    const float* out_w   = (const float*)d_in[9];
    const float* out_b   = (const float*)d_in[10];
    const float* ff_w1   = (const float*)d_in[11];
    const float* ff_b1   = (const float*)d_in[12];
    const float* ff_w2   = (const float*)d_in[13];
    const float* ff_b2   = (const float*)d_in[14];
    const float* ln1_g   = (const float*)d_in[15];
    const float* ln1_b   = (const float*)d_in[16];
    const float* ln2_g   = (const float*)d_in[17];
    const float* ln2_b   = (const float*)d_in[18];
    float* outp = (float*)d_out;

    float *pL, *ptmp1, *ptmp2, *pq, *pk, *pv, *poattn, *poproj, *pout1, *phidden;
    cudaGetSymbolAddress((void**)&pL,      g_L);
    cudaGetSymbolAddress((void**)&ptmp1,   g_tmp1);
    cudaGetSymbolAddress((void**)&ptmp2,   g_tmp2);
    cudaGetSymbolAddress((void**)&pq,      g_q);
    cudaGetSymbolAddress((void**)&pk,      g_k);
    cudaGetSymbolAddress((void**)&pv,      g_v);
    cudaGetSymbolAddress((void**)&poattn,  g_oattn);
    cudaGetSymbolAddress((void**)&poproj,  g_oproj);
    cudaGetSymbolAddress((void**)&pout1,   g_out1);
    cudaGetSymbolAddress((void**)&phidden, g_hidden);

    dim3 gG(NN, 3);
    gk1<<<gG, 256>>>(gl_w1, gl_w2, gl_beta, gl_cw, gl_cb, adj);
    gk2<<<gG, 256>>>();
    gk3<<<gG, 256>>>();
    gk4<<<gG, 256>>>();

    const long sBTD = (long)NN * DD;
    float* qkv[3] = {pq, pk, pv};
    dim3 gs(2, 3, BT);                 // spatial: N=120 (2 tiles), M=170 (3 tiles), 384 batches
    dim3 gc(2, (MTOK + 63) / 64, 1);   // channel: N=120, M=65280

    for (int i = 0; i < 3; i++) {
        const float* Li = pL + (size_t)i * NN * NN;
        const float* w  = cheb_w + (size_t)i * 3 * DD * DD;
        // tmp1 = L @ x (per batch)
        sgemm<<<gs, 256>>>(Li, x, ptmp1, nullptr, nullptr,
                           NN, DD, NN, 1.f, 0.f, 0, 0, sBTD, sBTD, 0);
        // tmp2 = 2*L @ tmp1 - x
        sgemm<<<gs, 256>>>(Li, ptmp1, ptmp2, x, nullptr,
                           NN, DD, NN, 2.f, -1.f, 0, 0, sBTD, sBTD, sBTD);
        // qkv_i = relu(x@w0 + tmp1@w1 + tmp2@w2 + bias)
        sgemm<<<gc, 256>>>(x, w, qkv[i], nullptr, nullptr,
                           MTOK, DD, DD, 1.f, 0.f, 0, 0, 0, 0, 0);
        sgemm<<<gc, 256>>>(ptmp1, w + DD*DD, qkv[i], nullptr, nullptr,
                           MTOK, DD, DD, 1.f, 0.f, FLAG_ACCUM, 0, 0, 0, 0);
        sgemm<<<gc, 256>>>(ptmp2, w + 2*DD*DD, qkv[i], nullptr, cheb_b + (size_t)i*DD,
                           MTOK, DD, DD, 1.f, 0.f, FLAG_ACCUM | FLAG_BIAS | FLAG_RELU,
                           0, 0, 0, 0);
    }

    attn_kernel<<<BB*NN, 128>>>(pq, pk, pv, poattn);

    // output projection: (B,N,T,D) rows
    sgemm<<<gc, 256>>>(poattn, out_w, poproj, nullptr, out_b,
                       MTOK, DD, DD, 1.f, 0.f, FLAG_BIAS, 0, 0, 0, 0);

    // LN1: out1 = LN(x + transpose(oproj))
    ln_kernel<<<MTOK/4, 128>>>(x, poproj, ln1_g, ln1_b, pout1, 1);

    // FFN
    dim3 gf1(FF/64, (MTOK + 63) / 64, 1);
    sgemm<<<gf1, 256>>>(pout1, ff_w1, phidden, nullptr, ff_b1,
                        MTOK, FF, DD, 1.f, 0.f, FLAG_BIAS | FLAG_RELU, 0, 0, 0, 0);
    sgemm<<<gc, 256>>>(phidden, ff_w2, ptmp1, nullptr, ff_b2,
                       MTOK, DD, FF, 1.f, 0.f, FLAG_BIAS, 0, 0, 0, 0);

    // LN2: out = LN(out1 + ffn)
    ln_kernel<<<MTOK/4, 128>>>(pout1, ptmp1, ln2_g, ln2_b, outp, 0);
}

// round 2
// speedup vs baseline: 1.4321x; 1.4321x over previous
#include <cuda_runtime.h>
#include <math.h>

#define NN 170
#define NKPAD 176
#define TT 12
#define BB 32
#define DD 120
#define HH 8
#define HD 15
#define FF 2048
#define BT (BB*TT)          // 384
#define MTOK (BB*TT*NN)     // 65280
#define NCOL (BT*DD)        // 46080 (columns of transposed activations)

#define FLAG_BIAS  2
#define FLAG_RELU  4

// ------------------------- static device scratch -------------------------
__device__ float g_L[3*NN*NKPAD];              // padded Laplacian, cols 170..175 zero
__device__ float g_A[3*NN*NN];
__device__ float g_rs0[3*NN];
__device__ float g_rs1[3*NN];
__device__ float g_xt [(size_t)NKPAD*NCOL];    // x transposed (node, bt*D+d); rows 170..175 stay zero
__device__ float g_t1t[(size_t)NKPAD*NCOL];    // T1 x transposed; rows 170..175 stay zero
__device__ float g_t2t[(size_t)NN*NCOL];       // T2 x transposed (also reused as FFN output buffer)
__device__ float g_xcat[(size_t)MTOK*360];     // [x | T1x | T2x] per token, token order (n, bt)
__device__ float g_q[(size_t)MTOK*DD];
__device__ float g_k[(size_t)MTOK*DD];
__device__ float g_v[(size_t)MTOK*DD];
__device__ float g_oattn[(size_t)MTOK*DD];     // (bt, n, d)
__device__ float g_oproj[(size_t)MTOK*DD];
__device__ float g_out1[(size_t)MTOK*DD];
__device__ float g_hidden[(size_t)MTOK*FF];

// ------------------------- f32x2 helpers -------------------------
__device__ __forceinline__ void fma2(unsigned long long &acc, unsigned long long a, unsigned long long b) {
    asm("fma.rn.f32x2 %0, %1, %2, %0;" : "+l"(acc) : "l"(a), "l"(b));
}
__device__ __forceinline__ unsigned long long pack2(float v) {
    unsigned long long r;
    unsigned int u = __float_as_uint(v);
    asm("mov.b64 %0, {%1, %1};" : "=l"(r) : "r"(u));
    return r;
}
__device__ __forceinline__ void unpack2(unsigned long long p, float &lo, float &hi) {
    unsigned int a, b;
    asm("mov.b64 {%0, %1}, %2;" : "=r"(a), "=r"(b) : "l"(p));
    lo = __uint_as_float(a); hi = __uint_as_float(b);
}

// ------------------------- graph learning kernels -------------------------
__global__ void gk1(const float* __restrict__ w1, const float* __restrict__ w2,
                    const float* __restrict__ beta, const float* __restrict__ cw,
                    const float* __restrict__ cb, const float* __restrict__ adj) {
    int r = blockIdx.x, br = blockIdx.y;
    __shared__ float w1r[DD], w2r[DD];
    __shared__ float red[256];
    const float* W1 = w1 + (size_t)br*NN*DD;
    const float* W2 = w2 + (size_t)br*NN*DD;
    for (int i = threadIdx.x; i < DD; i += blockDim.x) {
        w1r[i] = W1[r*DD + i];
        w2r[i] = W2[r*DD + i];
    }
    __syncthreads();
    float cw0 = cw[br*2+0], cw1 = cw[br*2+1], cbv = cb[br];
    float mysum = 0.f;
    for (int c = threadIdx.x; c < NN; c += blockDim.x) {
        const float* w1c = W1 + c*DD;
        const float* w2c = W2 + c*DD;
        float d1 = 0.f, d2 = 0.f;
        for (int e = 0; e < DD; e++) {
            d1 += w1r[e] * w2c[e];
            d2 += w2r[e] * w1c[e];
        }
        float nw = d1 - d2;
        if (r == c) nw += beta[br*NN + r];
        nw = fmaxf(nw, 0.f);
        float ad = adj[r*NN + c];
        float z = cw0*nw + cw1*ad + cbv;
        float gate = 1.f / (1.f + expf(-z));
        float a = gate*nw + (1.f - gate)*ad;
        g_A[(size_t)br*NN*NN + (size_t)r*NN + c] = a;
        mysum += a;
    }
    red[threadIdx.x] = mysum;
    __syncthreads();
    for (int s = 128; s > 0; s >>= 1) {
        if (threadIdx.x < s) red[threadIdx.x] += red[threadIdx.x + s];
        __syncthreads();
    }
    if (threadIdx.x == 0) g_rs0[br*NN + r] = red[0];
}

__global__ void gk2() {
    int r = blockIdx.x, br = blockIdx.y;
    __shared__ float red[256];
    float dr = rsqrtf(g_rs0[br*NN + r]);
    const float eps = 0.5f / (float)NN;
    float mysum = 0.f;
    for (int c = threadIdx.x; c < NN; c += blockDim.x) {
        float dc = rsqrtf(g_rs0[br*NN + c]);
        size_t idx = (size_t)br*NN*NN + (size_t)r*NN + c;
        float a = fmaxf(dr * g_A[idx] * dc - eps, 0.f);
        g_A[idx] = a;
        mysum += a;
    }
    red[threadIdx.x] = mysum;
    __syncthreads();
    for (int s = 128; s > 0; s >>= 1) {
        if (threadIdx.x < s) red[threadIdx.x] += red[threadIdx.x + s];
        __syncthreads();
    }
    if (threadIdx.x == 0) g_rs1[br*NN + r] = red[0];
}

__global__ void gk3() {
    int r = blockIdx.x, br = blockIdx.y;
    __shared__ float red[256];
    float dr = rsqrtf(g_rs1[br*NN + r]);
    float mysum = 0.f;
    for (int c = threadIdx.x; c < NN; c += blockDim.x) {
        float dc = rsqrtf(g_rs1[br*NN + c]);
        size_t idx = (size_t)br*NN*NN + (size_t)r*NN + c;
        float g = dr * g_A[idx] * dc;
        g_A[idx] = g;
        mysum += g;
    }
    red[threadIdx.x] = mysum;
    __syncthreads();
    for (int s = 128; s > 0; s >>= 1) {
        if (threadIdx.x < s) red[threadIdx.x] += red[threadIdx.x + s];
        __syncthreads();
    }
    if (threadIdx.x == 0) g_rs0[br*NN + r] = red[0];
}

// L_pad = I - e_r * g * e_c, padded to NKPAD cols with zeros
__global__ void gk4() {
    int r = blockIdx.x, br = blockIdx.y;
    float er = rsqrtf(g_rs0[br*NN + r]);
    for (int c = threadIdx.x; c < NKPAD; c += blockDim.x) {
        float L = 0.f;
        if (c < NN) {
            float ec = rsqrtf(g_rs0[br*NN + c]);
            L = ((r == c) ? 1.f : 0.f) - er * g_A[(size_t)br*NN*NN + (size_t)r*NN + c] * ec;
        }
        g_L[(size_t)br*NN*NKPAD + (size_t)r*NKPAD + c] = L;
    }
}

// ------------------------- f32x2 SGEMM -------------------------
// C = alpha*(A@B) [+ gamma*E] [+ bias] [relu]
// A: MxK (lda), B: KxN (ldb), C: MxN (ldc), E same shape/ld as C.
// Requires K % 8 == 0, lda even, ldb/ldc % 4 == 0, col0-aligned float4 on B rows.
template<int BM>
__global__ __launch_bounds__(256) void sgemm2(
        const float* __restrict__ A, const float* __restrict__ B,
        float* __restrict__ C, const float* __restrict__ E,
        const float* __restrict__ bias,
        int M, int N, int K, int lda, int ldb, int ldc,
        float alpha, float gamma, int flags)
{
    constexpr int TM = BM / 16;          // 8 for BM=128, 4 for BM=64
    constexpr int NA = (BM * 4) / 256;   // float2 A-loads per thread
    __shared__ float As[2][8][BM + 4];
    __shared__ float Bs[2][8][132];

    const int tid = threadIdx.x;
    const int tx = tid & 15, ty = tid >> 4;
    const int row0 = blockIdx.y * BM, col0 = blockIdx.x * 128;
    const bool fullN = (col0 + 128 <= N);
    const int nkt = K >> 3;

    const int bk = tid >> 5, bn = (tid & 31) * 4;

    unsigned long long acc[TM][4];
    #pragma unroll
    for (int i = 0; i < TM; i++)
        #pragma unroll
        for (int j = 0; j < 4; j++) acc[i][j] = 0ull;

    float2 ra[NA];
    float4 rb;

    // ---- load tile 0 directly into smem[0]
    #pragma unroll
    for (int it = 0; it < NA; it++) {
        int i = tid + it * 256;
        int arow = i >> 2, kp = i & 3;
        int gr = row0 + arow;
        float2 v = make_float2(0.f, 0.f);
        if (gr < M) v = *(const float2*)(A + (size_t)gr * lda + kp * 2);
        As[0][kp*2][arow]   = v.x;
        As[0][kp*2+1][arow] = v.y;
    }
    {
        const float* bp = B + (size_t)bk * ldb + col0 + bn;
        float4 v;
        if (fullN) v = *(const float4*)bp;
        else {
            v.x = (col0+bn+0 < N) ? bp[0] : 0.f;
            v.y = (col0+bn+1 < N) ? bp[1] : 0.f;
            v.z = (col0+bn+2 < N) ? bp[2] : 0.f;
            v.w = (col0+bn+3 < N) ? bp[3] : 0.f;
        }
        *(float4*)&Bs[0][bk][bn] = v;
    }
    __syncthreads();

    int buf = 0;
    for (int kt = 0; kt < nkt; kt++) {
        const bool has_next = (kt + 1 < nkt);
        if (has_next) {
            int k0 = (kt + 1) * 8;
            #pragma unroll
            for (int it = 0; it < NA; it++) {
                int i = tid + it * 256;
                int arow = i >> 2, kp = i & 3;
                int gr = row0 + arow;
                ra[it] = make_float2(0.f, 0.f);
                if (gr < M) ra[it] = *(const float2*)(A + (size_t)gr * lda + k0 + kp * 2);
            }
            const float* bp = B + (size_t)(k0 + bk) * ldb + col0 + bn;
            if (fullN) rb = *(const float4*)bp;
            else {
                rb.x = (col0+bn+0 < N) ? bp[0] : 0.f;
                rb.y = (col0+bn+1 < N) ? bp[1] : 0.f;
                rb.z = (col0+bn+2 < N) ? bp[2] : 0.f;
                rb.w = (col0+bn+3 < N) ? bp[3] : 0.f;
            }
        }

        #pragma unroll
        for (int k = 0; k < 8; k++) {
            float4 av0 = *(const float4*)&As[buf][k][ty * TM];
            float4 av1;
            if constexpr (TM == 8) av1 = *(const float4*)&As[buf][k][ty * TM + 4];
            ulonglong2 bv0 = *(const ulonglong2*)&Bs[buf][k][tx * 8];
            ulonglong2 bv1 = *(const ulonglong2*)&Bs[buf][k][tx * 8 + 4];
            float aarr[TM];
            aarr[0] = av0.x; aarr[1] = av0.y; aarr[2] = av0.z; aarr[3] = av0.w;
            if constexpr (TM == 8) { aarr[4] = av1.x; aarr[5] = av1.y; aarr[6] = av1.z; aarr[7] = av1.w; }
            #pragma unroll
            for (int i = 0; i < TM; i++) {
                unsigned long long aa = pack2(aarr[i]);
                fma2(acc[i][0], aa, bv0.x);
                fma2(acc[i][1], aa, bv0.y);
                fma2(acc[i][2], aa, bv1.x);
                fma2(acc[i][3], aa, bv1.y);
            }
        }

        if (has_next) {
            int nb = buf ^ 1;
            #pragma unroll
            for (int it = 0; it < NA; it++) {
                int i = tid + it * 256;
                int arow = i >> 2, kp = i & 3;
                As[nb][kp*2][arow]   = ra[it].x;
                As[nb][kp*2+1][arow] = ra[it].y;
            }
            *(float4*)&Bs[nb][bk][bn] = rb;
        }
        __syncthreads();
        buf ^= 1;
    }

    // ---- epilogue
    #pragma unroll
    for (int i = 0; i < TM; i++) {
        int gr = row0 + ty * TM + i;
        if (gr >= M) continue;
        float* crow = C + (size_t)gr * ldc;
        const float* erow = E ? (E + (size_t)gr * ldc) : nullptr;
        #pragma unroll
        for (int j = 0; j < 4; j++) {
            float lo, hi;
            unpack2(acc[i][j], lo, hi);
            int gc0 = col0 + tx * 8 + j * 2;
            #pragma unroll
            for (int s = 0; s < 2; s++) {
                int gc = gc0 + s;
                if (gc >= N) continue;
                float v = alpha * (s ? hi : lo);
                if (erow) v += gamma * erow[gc];
                if (flags & FLAG_BIAS) v += bias[gc];
                if (flags & FLAG_RELU) v = fmaxf(v, 0.f);
                crow[gc] = v;
            }
        }
    }
}

// ------------------------- layout kernels -------------------------
// xt[(n*BT+bt)*D + d] = x[(bt*NN+n)*D + d]
__global__ void transpose_x(const float* __restrict__ x, float* __restrict__ xt) {
    int idx = blockIdx.x;
    int bt = idx / NN, n = idx % NN;
    const float* src = x + (size_t)idx * DD;
    float* dst = xt + ((size_t)n * BT + bt) * DD;
    for (int d = threadIdx.x; d < DD; d += blockDim.x) dst[d] = src[d];
}

// xcat[r*360 + 0..119] = xt[r*120..]   (done once)
__global__ void pack_x(const float* __restrict__ xt, float* __restrict__ xcat) {
    size_t r = blockIdx.x;
    const float* s = xt + r * DD;
    float* d = xcat + r * 360;
    for (int i = threadIdx.x; i < DD; i += blockDim.x) d[i] = s[i];
}

// xcat[r*360 + 120..359] = [t1t, t2t]  (per branch)
__global__ void pack12(const float* __restrict__ t1, const float* __restrict__ t2,
                       float* __restrict__ xcat) {
    size_t r = blockIdx.x;
    const float* s1 = t1 + r * DD;
    const float* s2 = t2 + r * DD;
    float* d = xcat + r * 360;
    for (int i = threadIdx.x; i < DD; i += blockDim.x) {
        d[120 + i] = s1[i];
        d[240 + i] = s2[i];
    }
}

// ------------------------- attention -------------------------
// q,k,v layout (n, bt, d). Output o layout (bt, n, d).
__global__ void attn_kernel(const float* __restrict__ q, const float* __restrict__ k,
                            const float* __restrict__ v, float* __restrict__ o) {
    int bn = blockIdx.x;
    int b = bn / NN, n = bn % NN;
    __shared__ float qs[TT][DD], ks[TT][DD], vs[TT][DD];
    size_t base = ((size_t)n * BT + (size_t)b * TT) * DD;
    for (int i = threadIdx.x; i < TT*DD; i += blockDim.x) {
        qs[i / DD][i % DD] = q[base + i];
        ks[i / DD][i % DD] = k[base + i];
        vs[i / DD][i % DD] = v[base + i];
    }
    __syncthreads();
    int tid = threadIdx.x;
    if (tid < HH*TT) {
        int h = tid / TT, qi = tid % TT;
        const float scale = rsqrtf((float)HD);
        float s[TT];
        float mx = -1e30f;
        #pragma unroll
        for (int j = 0; j < TT; j++) {
            float acc = 0.f;
            #pragma unroll
            for (int e = 0; e < HD; e++) acc += qs[qi][h*HD + e] * ks[j][h*HD + e];
            acc *= scale;
            s[j] = acc;
            mx = fmaxf(mx, acc);
        }
        float sum = 0.f;
        #pragma unroll
        for (int j = 0; j < TT; j++) { s[j] = expf(s[j] - mx); sum += s[j]; }
        float inv = 1.f / sum;
        size_t obase = (((size_t)(b*TT + qi)) * NN + n) * DD + h*HD;
        #pragma unroll
        for (int e = 0; e < HD; e++) {
            float acc = 0.f;
            #pragma unroll
            for (int j = 0; j < TT; j++) acc += s[j] * vs[j][h*HD + e];
            o[obase + e] = acc * inv;
        }
    }
}

// ------------------------- fused residual + layernorm -------------------------
__global__ void ln_kernel(const float* __restrict__ xa, const float* __restrict__ xb,
                          const float* __restrict__ gg, const float* __restrict__ bb,
                          float* __restrict__ outp) {
    int warp = threadIdx.x >> 5, lane = threadIdx.x & 31;
    size_t m = (size_t)blockIdx.x * 4 + warp;
    if (m >= MTOK) return;
    size_t ia = m * DD;
    float v[4];
    float s = 0.f;
    #pragma unroll
    for (int i = 0; i < 4; i++) {
        int d = lane + 32*i;
        float val = (d < DD) ? (xa[ia + d] + xb[ia + d]) : 0.f;
        v[i] = val;
        s += val;
    }
    #pragma unroll
    for (int o = 16; o > 0; o >>= 1) s += __shfl_xor_sync(0xffffffffu, s, o);
    float mean = s * (1.f / DD);
    float vsum = 0.f;
    #pragma unroll
    for (int i = 0; i < 4; i++) {
        int d = lane + 32*i;
        if (d < DD) { float df = v[i] - mean; vsum += df*df; }
    }
    #pragma unroll
    for (int o = 16; o > 0; o >>= 1) vsum += __shfl_xor_sync(0xffffffffu, vsum, o);
    float inv = rsqrtf(vsum * (1.f / DD) + 1e-5f);
    #pragma unroll
    for (int i = 0; i < 4; i++) {
        int d = lane + 32*i;
        if (d < DD) outp[ia + d] = (v[i] - mean) * inv * gg[d] + bb[d];
    }
}

// ------------------------- launch -------------------------
extern "C" void kernel_launch(void* const* d_in, const int* in_sizes, int n_in,
                              void* d_out, int out_size) {
    const float* x       = (const float*)d_in[0];
    const float* adj     = (const float*)d_in[1];
    const float* gl_beta = (const float*)d_in[2];
    const float* gl_w1   = (const float*)d_in[3];
    const float* gl_w2   = (const float*)d_in[4];
    const float* gl_cw   = (const float*)d_in[5];
    const float* gl_cb   = (const float*)d_in[6];
    const float* cheb_w  = (const float*)d_in[7];
    const float* cheb_b  = (const float*)d_in[8];
    const float* out_w   = (const float*)d_in[9];
    const float* out_b   = (const float*)d_in[10];
    const float* ff_w1   = (const float*)d_in[11];
    const float* ff_b1   = (const float*)d_in[12];
    const float* ff_w2   = (const float*)d_in[13];
    const float* ff_b2   = (const float*)d_in[14];
    const float* ln1_g   = (const float*)d_in[15];
    const float* ln1_b   = (const float*)d_in[16];
    const float* ln2_g   = (const float*)d_in[17];
    const float* ln2_b   = (const float*)d_in[18];
    float* outp = (float*)d_out;

    float *pL, *pxt, *pt1, *pt2, *pxcat, *pq, *pk, *pv, *poattn, *poproj, *pout1, *phidden;
    cudaGetSymbolAddress((void**)&pL,      g_L);
    cudaGetSymbolAddress((void**)&pxt,     g_xt);
    cudaGetSymbolAddress((void**)&pt1,     g_t1t);
    cudaGetSymbolAddress((void**)&pt2,     g_t2t);
    cudaGetSymbolAddress((void**)&pxcat,   g_xcat);
    cudaGetSymbolAddress((void**)&pq,      g_q);
    cudaGetSymbolAddress((void**)&pk,      g_k);
    cudaGetSymbolAddress((void**)&pv,      g_v);
    cudaGetSymbolAddress((void**)&poattn,  g_oattn);
    cudaGetSymbolAddress((void**)&poproj,  g_oproj);
    cudaGetSymbolAddress((void**)&pout1,   g_out1);
    cudaGetSymbolAddress((void**)&phidden, g_hidden);

    // graph learning (3 branches)
    dim3 gG(NN, 3);
    gk1<<<gG, 256>>>(gl_w1, gl_w2, gl_beta, gl_cw, gl_cb, adj);
    gk2<<<gG, 256>>>();
    gk3<<<gG, 256>>>();
    gk4<<<gG, 256>>>();

    // layout prep
    transpose_x<<<MTOK, 128>>>(x, pxt);
    pack_x<<<MTOK, 128>>>(pxt, pxcat);

    float* qkv[3] = {pq, pk, pv};
    dim3 gs(NCOL/128, (NN + 63) / 64);   // spatial: 360 x 3
    dim3 gc(1, MTOK/128);                // channel N=120: 1 x 510

    for (int i = 0; i < 3; i++) {
        const float* Li = pL + (size_t)i * NN * NKPAD;
        // t1 = L @ xt          (170 x 46080, K=176 padded)
        sgemm2<64><<<gs, 256>>>(Li, pxt, pt1, nullptr, nullptr,
                                NN, NCOL, NKPAD, NKPAD, NCOL, NCOL, 1.f, 0.f, 0);
        // t2 = 2*L @ t1 - xt
        sgemm2<64><<<gs, 256>>>(Li, pt1, pt2, pxt, nullptr,
                                NN, NCOL, NKPAD, NKPAD, NCOL, NCOL, 2.f, -1.f, 0);
        pack12<<<MTOK, 128>>>(pt1, pt2, pxcat);
        // qkv_i = relu(xcat @ W_i + b_i), K=360
        sgemm2<128><<<gc, 256>>>(pxcat, cheb_w + (size_t)i*360*DD, qkv[i], nullptr,
                                 cheb_b + (size_t)i*DD,
                                 MTOK, DD, 360, 360, DD, DD, 1.f, 0.f,
                                 FLAG_BIAS | FLAG_RELU);
    }

    attn_kernel<<<BB*NN, 128>>>(pq, pk, pv, poattn);

    // output projection (tokens in (bt,n) order now)
    sgemm2<128><<<gc, 256>>>(poattn, out_w, poproj, nullptr, out_b,
                             MTOK, DD, DD, DD, DD, DD, 1.f, 0.f, FLAG_BIAS);

    // LN1: out1 = LN(x + oproj)
    ln_kernel<<<MTOK/4, 128>>>(x, poproj, ln1_g, ln1_b, pout1);

    // FFN
    dim3 gf1(FF/128, MTOK/128);
    sgemm2<128><<<gf1, 256>>>(pout1, ff_w1, phidden, nullptr, ff_b1,
                              MTOK, FF, DD, DD, FF, FF, 1.f, 0.f,
                              FLAG_BIAS | FLAG_RELU);
    // reuse pt2 (31.3MB) as FFN output buffer
    sgemm2<128><<<gc, 256>>>(phidden, ff_w2, pt2, nullptr, ff_b2,
                             MTOK, DD, FF, FF, DD, DD, 1.f, 0.f, FLAG_BIAS);

    // LN2: out = LN(out1 + ffn)
    ln_kernel<<<MTOK/4, 128>>>(pout1, pt2, ln2_g, ln2_b, outp);
}

// round 5
// speedup vs baseline: 1.9805x; 1.3830x over previous
#include <cuda_runtime.h>
#include <cuda_bf16.h>
#include <math.h>
#include <stdint.h>

#define NN 170
#define NKP 192            // padded node dim (K for spatial GEMM)
#define NROWP 192          // padded L rows (B operand tiles: 3 x 64)
#define TT 12
#define BB 32
#define DD 120
#define HH 8
#define HD 15
#define FF 2048
#define BT (BB*TT)          // 384
#define MTOK (BB*TT*NN)     // 65280 = 510*128
#define MSP (BT*DD)         // 46080 = 360*128

#define FLAG_BIAS  1
#define FLAG_RELU  2
#define FLAG_T2    4        // epilogue: v = 2*acc - (Xh+Xl)

// ------------------------- static device scratch (zero-initialized) --------
__device__ float g_A[3*NN*NN];
__device__ float g_rs0[3*NN];
__device__ float g_rs1[3*NN];

__device__ __align__(16) __nv_bfloat16 g_Lh[3*NROWP*NKP];   // rows 170..191 zero
__device__ __align__(16) __nv_bfloat16 g_Ll[3*NROWP*NKP];
__device__ __align__(16) __nv_bfloat16 g_xth[(size_t)MSP*NKP];
__device__ __align__(16) __nv_bfloat16 g_xtl[(size_t)MSP*NKP];
__device__ __align__(16) __nv_bfloat16 g_t1h[(size_t)MSP*NKP];
__device__ __align__(16) __nv_bfloat16 g_t1l[(size_t)MSP*NKP];
__device__ __align__(16) __nv_bfloat16 g_t2h[(size_t)MSP*NKP];
__device__ __align__(16) __nv_bfloat16 g_t2l[(size_t)MSP*NKP];
__device__ __align__(16) __nv_bfloat16 g_xcath[(size_t)MTOK*384];
__device__ __align__(16) __nv_bfloat16 g_xcatl[(size_t)MTOK*384];
__device__ __align__(16) __nv_bfloat16 g_oah[(size_t)MTOK*128];
__device__ __align__(16) __nv_bfloat16 g_oal[(size_t)MTOK*128];
__device__ __align__(16) __nv_bfloat16 g_o1h[(size_t)MTOK*128];
__device__ __align__(16) __nv_bfloat16 g_o1l[(size_t)MTOK*128];
__device__ __align__(16) __nv_bfloat16 g_hidh[(size_t)MTOK*FF];
__device__ __align__(16) __nv_bfloat16 g_hidl[(size_t)MTOK*FF];
// B-operand weights, padded to 128 rows
__device__ __align__(16) __nv_bfloat16 g_wqh[3*128*384];
__device__ __align__(16) __nv_bfloat16 g_wql[3*128*384];
__device__ __align__(16) __nv_bfloat16 g_owh[128*128];
__device__ __align__(16) __nv_bfloat16 g_owl[128*128];
__device__ __align__(16) __nv_bfloat16 g_w1h[(size_t)FF*128];
__device__ __align__(16) __nv_bfloat16 g_w1l[(size_t)FF*128];
__device__ __align__(16) __nv_bfloat16 g_w2h[(size_t)128*FF];
__device__ __align__(16) __nv_bfloat16 g_w2l[(size_t)128*FF];
__device__ float g_q[(size_t)MTOK*DD];
__device__ float g_k[(size_t)MTOK*DD];
__device__ float g_v[(size_t)MTOK*DD];
__device__ float g_oproj[(size_t)MTOK*DD];
__device__ float g_out1f[(size_t)MTOK*DD];
__device__ float g_ffnf[(size_t)MTOK*DD];

// ------------------------- helpers -------------------------
__device__ __forceinline__ void bsplit(float v, __nv_bfloat16 &h, __nv_bfloat16 &l) {
    h = __float2bfloat16_rn(v);
    l = __float2bfloat16_rn(v - __bfloat162float(h));
}
__device__ __forceinline__ uint32_t smem_u32(const void* p) {
    uint32_t a;
    asm("{ .reg .u64 t; cvta.to.shared.u64 t, %1; cvt.u32.u64 %0, t; }" : "=r"(a) : "l"(p));
    return a;
}
__device__ __forceinline__ void ldm4(uint32_t (&d)[4], uint32_t addr) {
    asm volatile("ldmatrix.sync.aligned.m8n8.x4.shared.b16 {%0,%1,%2,%3}, [%4];"
                 : "=r"(d[0]), "=r"(d[1]), "=r"(d[2]), "=r"(d[3]) : "r"(addr));
}
__device__ __forceinline__ void mma16816(float (&c)[4], const uint32_t (&a)[4],
                                         uint32_t b0, uint32_t b1) {
    asm volatile("mma.sync.aligned.m16n8k16.row.col.f32.bf16.bf16.f32 "
                 "{%0,%1,%2,%3}, {%4,%5,%6,%7}, {%8,%9}, {%0,%1,%2,%3};"
                 : "+f"(c[0]), "+f"(c[1]), "+f"(c[2]), "+f"(c[3])
                 : "r"(a[0]), "r"(a[1]), "r"(a[2]), "r"(a[3]), "r"(b0), "r"(b1));
}

// ------------------------- HMMA bf16x3 GEMM -------------------------
// D[M,N] = sum_k A[m,k]*B[n,k]; A: M x K (lda), B: (>= gridDim.y*BN rows) x K (ldb).
// K%16==0, M%128==0, all B rows up to tile boundary readable (zero-padded).
// Output: fp32 Cf or bf16 hi/lo Ch/Cl, ldc, cols < Nout.
template<int BN>
__global__ __launch_bounds__(256) void hmma_bf16x3(
        const __nv_bfloat16* __restrict__ Ah, const __nv_bfloat16* __restrict__ Al, int lda,
        const __nv_bfloat16* __restrict__ Bh, const __nv_bfloat16* __restrict__ Bl, int ldb,
        int K,
        float* __restrict__ Cf, __nv_bfloat16* __restrict__ Ch, __nv_bfloat16* __restrict__ Cl,
        int ldc, int Nout,
        const float* __restrict__ bias, int flags,
        const __nv_bfloat16* __restrict__ Xh, const __nv_bfloat16* __restrict__ Xl)
{
    constexpr int A16 = 128*3;          // 16B units per A matrix (48B row pitch)
    constexpr int B16 = BN*3;
    constexpr int NB = (BN*4)/256;      // B uint4 per thread
    constexpr int WN = BN / 2;
    constexpr int NP = WN / 16;
    constexpr int BH = BN * 2;

    extern __shared__ __align__(16) char smem[];
    const uint32_t sbase = smem_u32(smem);
    const int tid = threadIdx.x;
    const int lane = tid & 31;
    const int wid = tid >> 5;
    const int wm = wid & 3, wn = wid >> 2;
    const int row0 = blockIdx.x * 128;
    const int col0 = blockIdx.y * BN;

    float acc[2][2*NP][4];
    #pragma unroll
    for (int i = 0; i < 2; i++)
        #pragma unroll
        for (int j = 0; j < 2*NP; j++)
            #pragma unroll
            for (int e = 0; e < 4; e++) acc[i][j][e] = 0.f;

    // per-thread ldmatrix offsets (bytes)
    const int arow = wm*32 + (lane & 15);
    const int akc  = lane >> 4;
    const uint32_t aoff = (uint32_t)(arow*3 + akc) * 16;
    const int brow = wn*WN + (lane & 7) + ((lane >> 4) & 1)*8;
    const int bkc  = (lane >> 3) & 1;
    const uint32_t boff = (uint32_t)(2*A16 + brow*3 + bkc) * 16;

    uint4 ra[2], rb[NB];

    auto gload = [&](int c) {
        const int k0 = c * 16;
        #pragma unroll
        for (int t = 0; t < 2; t++) {
            int i = tid + t*256;
            int mat = i >> 8, u = i & 255, r = u >> 1, kc = u & 1;
            ra[t] = *(const uint4*)((mat ? Al : Ah) + (size_t)(row0 + r)*lda + k0 + kc*8);
        }
        #pragma unroll
        for (int t = 0; t < NB; t++) {
            int i = tid + t*256;
            int mat = i / BH, u = i % BH, r = u >> 1, kc = u & 1;
            rb[t] = *(const uint4*)((mat ? Bl : Bh) + (size_t)(col0 + r)*ldb + k0 + kc*8);
        }
    };
    auto sstore = [&]() {
        #pragma unroll
        for (int t = 0; t < 2; t++) {
            int i = tid + t*256;
            int mat = i >> 8, u = i & 255, r = u >> 1, kc = u & 1;
            *(uint4*)(smem + (uint32_t)(mat*A16 + r*3 + kc)*16) = ra[t];
        }
        #pragma unroll
        for (int t = 0; t < NB; t++) {
            int i = tid + t*256;
            int mat = i / BH, u = i % BH, r = u >> 1, kc = u & 1;
            *(uint4*)(smem + (uint32_t)(2*A16 + mat*B16 + r*3 + kc)*16) = rb[t];
        }
    };

    const int nch = K >> 4;
    gload(0);

    for (int c = 0; c < nch; c++) {
        __syncthreads();                 // previous compute done reading smem
        sstore();
        if (c + 1 < nch) gload(c + 1);   // overlap next global load with compute
        __syncthreads();                 // smem tile visible

        uint32_t ahf[2][4], alf[2][4];
        #pragma unroll
        for (int mi = 0; mi < 2; mi++) {
            uint32_t ad = sbase + aoff + (uint32_t)mi * 768;   // +16 rows
            ldm4(ahf[mi], ad);
            ldm4(alf[mi], ad + A16*16);
        }
        uint32_t bhf[NP][4], blf[NP][4];
        #pragma unroll
        for (int np = 0; np < NP; np++) {
            uint32_t bd = sbase + boff + (uint32_t)np * 768;
            ldm4(bhf[np], bd);
            ldm4(blf[np], bd + B16*16);
        }
        #pragma unroll
        for (int mi = 0; mi < 2; mi++)
            #pragma unroll
            for (int np = 0; np < NP; np++)
                #pragma unroll
                for (int hf = 0; hf < 2; hf++) {
                    int na = np*2 + hf;
                    mma16816(acc[mi][na], ahf[mi], bhf[np][2*hf], bhf[np][2*hf+1]);
                    mma16816(acc[mi][na], ahf[mi], blf[np][2*hf], blf[np][2*hf+1]);
                    mma16816(acc[mi][na], alf[mi], bhf[np][2*hf], bhf[np][2*hf+1]);
                }
    }

    // ---- epilogue
    const int lr = lane >> 2, lc = (lane & 3) * 2;
    #pragma unroll
    for (int mi = 0; mi < 2; mi++) {
        #pragma unroll
        for (int na = 0; na < 2*NP; na++) {
            int gr0 = row0 + wm*32 + mi*16 + lr;
            int gc0 = col0 + wn*WN + na*8 + lc;
            #pragma unroll
            for (int e = 0; e < 4; e++) {
                int gr = gr0 + (e >> 1) * 8;
                int gc = gc0 + (e & 1);
                if (gc >= Nout) continue;
                float v = acc[mi][na][e];
                size_t ci = (size_t)gr * ldc + gc;
                if (flags & FLAG_T2)
                    v = 2.f*v - (__bfloat162float(Xh[ci]) + __bfloat162float(Xl[ci]));
                if (flags & FLAG_BIAS) v += bias[gc];
                if (flags & FLAG_RELU) v = fmaxf(v, 0.f);
                if (Cf) Cf[ci] = v;
                else { __nv_bfloat16 h, l; bsplit(v, h, l); Ch[ci] = h; Cl[ci] = l; }
            }
        }
    }
}

// ------------------------- graph learning -------------------------
__global__ void gk1(const float* __restrict__ w1, const float* __restrict__ w2,
                    const float* __restrict__ beta, const float* __restrict__ cw,
                    const float* __restrict__ cb, const float* __restrict__ adj) {
    int r = blockIdx.x, br = blockIdx.y;
    __shared__ float w1r[DD], w2r[DD];
    __shared__ float red[256];
    const float* W1 = w1 + (size_t)br*NN*DD;
    const float* W2 = w2 + (size_t)br*NN*DD;
    for (int i = threadIdx.x; i < DD; i += blockDim.x) { w1r[i] = W1[r*DD+i]; w2r[i] = W2[r*DD+i]; }
    __syncthreads();
    float cw0 = cw[br*2+0], cw1 = cw[br*2+1], cbv = cb[br];
    float mysum = 0.f;
    for (int c = threadIdx.x; c < NN; c += blockDim.x) {
        const float* w1c = W1 + c*DD;
        const float* w2c = W2 + c*DD;
        float d1 = 0.f, d2 = 0.f;
        for (int e = 0; e < DD; e++) { d1 += w1r[e]*w2c[e]; d2 += w2r[e]*w1c[e]; }
        float nw = d1 - d2;
        if (r == c) nw += beta[br*NN + r];
        nw = fmaxf(nw, 0.f);
        float ad = adj[r*NN + c];
        float gate = 1.f / (1.f + expf(-(cw0*nw + cw1*ad + cbv)));
        float a = gate*nw + (1.f - gate)*ad;
        g_A[(size_t)br*NN*NN + (size_t)r*NN + c] = a;
        mysum += a;
    }
    red[threadIdx.x] = mysum; __syncthreads();
    for (int s = 128; s > 0; s >>= 1) { if (threadIdx.x < s) red[threadIdx.x] += red[threadIdx.x+s]; __syncthreads(); }
    if (threadIdx.x == 0) g_rs0[br*NN + r] = red[0];
}
__global__ void gk2() {
    int r = blockIdx.x, br = blockIdx.y;
    __shared__ float red[256];
    float dr = rsqrtf(g_rs0[br*NN + r]);
    const float eps = 0.5f / (float)NN;
    float mysum = 0.f;
    for (int c = threadIdx.x; c < NN; c += blockDim.x) {
        float dc = rsqrtf(g_rs0[br*NN + c]);
        size_t idx = (size_t)br*NN*NN + (size_t)r*NN + c;
        float a = fmaxf(dr * g_A[idx] * dc - eps, 0.f);
        g_A[idx] = a; mysum += a;
    }
    red[threadIdx.x] = mysum; __syncthreads();
    for (int s = 128; s > 0; s >>= 1) { if (threadIdx.x < s) red[threadIdx.x] += red[threadIdx.x+s]; __syncthreads(); }
    if (threadIdx.x == 0) g_rs1[br*NN + r] = red[0];
}
__global__ void gk3() {
    int r = blockIdx.x, br = blockIdx.y;
    __shared__ float red[256];
    float dr = rsqrtf(g_rs1[br*NN + r]);
    float mysum = 0.f;
    for (int c = threadIdx.x; c < NN; c += blockDim.x) {
        float dc = rsqrtf(g_rs1[br*NN + c]);
        size_t idx = (size_t)br*NN*NN + (size_t)r*NN + c;
        float g = dr * g_A[idx] * dc;
        g_A[idx] = g; mysum += g;
    }
    red[threadIdx.x] = mysum; __syncthreads();
    for (int s = 128; s > 0; s >>= 1) { if (threadIdx.x < s) red[threadIdx.x] += red[threadIdx.x+s]; __syncthreads(); }
    if (threadIdx.x == 0) g_rs0[br*NN + r] = red[0];
}
__global__ void gk4() {
    int r = blockIdx.x, br = blockIdx.y;
    float er = rsqrtf(g_rs0[br*NN + r]);
    for (int c = threadIdx.x; c < NKP; c += blockDim.x) {
        float L = 0.f;
        if (c < NN) {
            float ec = rsqrtf(g_rs0[br*NN + c]);
            L = ((r == c) ? 1.f : 0.f) - er * g_A[(size_t)br*NN*NN + (size_t)r*NN + c] * ec;
        }
        __nv_bfloat16 h, l; bsplit(L, h, l);
        size_t idx = (size_t)br*NROWP*NKP + (size_t)r*NKP + c;
        g_Lh[idx] = h; g_Ll[idx] = l;
    }
}

// ------------------------- layout / split kernels -------------------------
__global__ void xsplitT(const float* __restrict__ x) {
    int row = blockIdx.x;               // bt*DD + d
    int bt = row / DD, d = row % DD;
    int n = threadIdx.x;
    if (n < NN) {
        float v = x[((size_t)bt*NN + n)*DD + d];
        __nv_bfloat16 h, l; bsplit(v, h, l);
        g_xth[(size_t)row*NKP + n] = h;
        g_xtl[(size_t)row*NKP + n] = l;
    }
}
__global__ void pack_x(const float* __restrict__ x) {
    size_t r = blockIdx.x;
    int d = threadIdx.x;
    if (d < DD) {
        __nv_bfloat16 h, l; bsplit(x[r*DD + d], h, l);
        g_xcath[r*384 + d] = h;
        g_xcatl[r*384 + d] = l;
    }
}
__global__ void pack12() {
    size_t r = blockIdx.x;
    int bt = (int)(r / NN), n = (int)(r % NN);
    int d = threadIdx.x;
    if (d < DD) {
        size_t ti = ((size_t)bt*DD + d)*NKP + n;
        g_xcath[r*384 + 120 + d] = g_t1h[ti];
        g_xcatl[r*384 + 120 + d] = g_t1l[ti];
        g_xcath[r*384 + 240 + d] = g_t2h[ti];
        g_xcatl[r*384 + 240 + d] = g_t2l[ti];
    }
}
__global__ void wsplit(const float* __restrict__ src, __nv_bfloat16* __restrict__ dh,
                       __nv_bfloat16* __restrict__ dl, int K, int N, int ldk) {
    int n = blockIdx.x;
    for (int k = threadIdx.x; k < K; k += blockDim.x) {
        __nv_bfloat16 h, l; bsplit(src[(size_t)k*N + n], h, l);
        dh[(size_t)n*ldk + k] = h;
        dl[(size_t)n*ldk + k] = l;
    }
}

// ------------------------- attention -------------------------
__global__ void attn_kernel(const float* __restrict__ q, const float* __restrict__ k,
                            const float* __restrict__ v) {
    int bn = blockIdx.x;
    int b = bn / NN, n = bn % NN;
    __shared__ float qs[TT][DD], ks[TT][DD], vs[TT][DD];
    for (int i = threadIdx.x; i < TT*DD; i += blockDim.x) {
        int t = i / DD, d = i % DD;
        size_t gi = (((size_t)(b*TT + t))*NN + n)*DD + d;
        qs[t][d] = q[gi]; ks[t][d] = k[gi]; vs[t][d] = v[gi];
    }
    __syncthreads();
    int tid = threadIdx.x;
    if (tid < HH*TT) {
        int h = tid / TT, qi = tid % TT;
        const float scale = rsqrtf((float)HD);
        float s[TT]; float mx = -1e30f;
        #pragma unroll
        for (int j = 0; j < TT; j++) {
            float acc = 0.f;
            #pragma unroll
            for (int e = 0; e < HD; e++) acc += qs[qi][h*HD+e] * ks[j][h*HD+e];
            acc *= scale; s[j] = acc; mx = fmaxf(mx, acc);
        }
        float sum = 0.f;
        #pragma unroll
        for (int j = 0; j < TT; j++) { s[j] = expf(s[j]-mx); sum += s[j]; }
        float inv = 1.f / sum;
        size_t orow = ((size_t)(b*TT + qi))*NN + n;
        #pragma unroll
        for (int e = 0; e < HD; e++) {
            float acc = 0.f;
            #pragma unroll
            for (int j = 0; j < TT; j++) acc += s[j] * vs[j][h*HD+e];
            __nv_bfloat16 hh, ll; bsplit(acc*inv, hh, ll);
            g_oah[orow*128 + h*HD + e] = hh;
            g_oal[orow*128 + h*HD + e] = ll;
        }
    }
}

// ------------------------- residual + layernorm -------------------------
__global__ void ln_kernel(const float* __restrict__ xa, const float* __restrict__ xb,
                          const float* __restrict__ gg, const float* __restrict__ bb,
                          float* __restrict__ outp, __nv_bfloat16* __restrict__ oh,
                          __nv_bfloat16* __restrict__ ol) {
    int warp = threadIdx.x >> 5, lane = threadIdx.x & 31;
    size_t m = (size_t)blockIdx.x * 4 + warp;
    if (m >= MTOK) return;
    size_t ia = m * DD;
    float v[4]; float s = 0.f;
    #pragma unroll
    for (int i = 0; i < 4; i++) {
        int d = lane + 32*i;
        float val = (d < DD) ? (xa[ia+d] + xb[ia+d]) : 0.f;
        v[i] = val; s += val;
    }
    #pragma unroll
    for (int o = 16; o > 0; o >>= 1) s += __shfl_xor_sync(0xffffffffu, s, o);
    float mean = s * (1.f / DD);
    float vsum = 0.f;
    #pragma unroll
    for (int i = 0; i < 4; i++) {
        int d = lane + 32*i;
        if (d < DD) { float df = v[i]-mean; vsum += df*df; }
    }
    #pragma unroll
    for (int o = 16; o > 0; o >>= 1) vsum += __shfl_xor_sync(0xffffffffu, vsum, o);
    float inv = rsqrtf(vsum * (1.f / DD) + 1e-5f);
    #pragma unroll
    for (int i = 0; i < 4; i++) {
        int d = lane + 32*i;
        if (d < DD) {
            float o = (v[i]-mean)*inv*gg[d] + bb[d];
            if (outp) outp[ia + d] = o;
            if (oh) { __nv_bfloat16 h, l; bsplit(o, h, l); oh[m*128 + d] = h; ol[m*128 + d] = l; }
        }
    }
}

// ------------------------- launch -------------------------
extern "C" void kernel_launch(void* const* d_in, const int* in_sizes, int n_in,
                              void* d_out, int out_size) {
    const float* x       = (const float*)d_in[0];
    const float* adj     = (const float*)d_in[1];
    const float* gl_beta = (const float*)d_in[2];
    const float* gl_w1   = (const float*)d_in[3];
    const float* gl_w2   = (const float*)d_in[4];
    const float* gl_cw   = (const float*)d_in[5];
    const float* gl_cb   = (const float*)d_in[6];
    const float* cheb_w  = (const float*)d_in[7];
    const float* cheb_b  = (const float*)d_in[8];
    const float* out_w   = (const float*)d_in[9];
    const float* out_b   = (const float*)d_in[10];
    const float* ff_w1   = (const float*)d_in[11];
    const float* ff_b1   = (const float*)d_in[12];
    const float* ff_w2   = (const float*)d_in[13];
    const float* ff_b2   = (const float*)d_in[14];
    const float* ln1_g   = (const float*)d_in[15];
    const float* ln1_b   = (const float*)d_in[16];
    const float* ln2_g   = (const float*)d_in[17];
    const float* ln2_b   = (const float*)d_in[18];
    float* outp = (float*)d_out;

    const int SMEM128 = (2*(128*3) + 2*(128*3)) * 16;   // 24576
    const int SMEM64  = (2*(128*3) + 2*(64*3)) * 16;    // 18432

    __nv_bfloat16 *pLh, *pLl, *pxth, *pxtl, *pt1h, *pt1l, *pt2h, *pt2l;
    __nv_bfloat16 *pxch, *pxcl, *poah, *poal, *po1h, *po1l, *phh, *phl;
    __nv_bfloat16 *pwqh, *pwql, *powh, *powl, *pw1h, *pw1l, *pw2h, *pw2l;
    float *pq, *pk, *pv, *poproj, *pout1f, *pffnf;
    cudaGetSymbolAddress((void**)&pLh, g_Lh);   cudaGetSymbolAddress((void**)&pLl, g_Ll);
    cudaGetSymbolAddress((void**)&pxth, g_xth); cudaGetSymbolAddress((void**)&pxtl, g_xtl);
    cudaGetSymbolAddress((void**)&pt1h, g_t1h); cudaGetSymbolAddress((void**)&pt1l, g_t1l);
    cudaGetSymbolAddress((void**)&pt2h, g_t2h); cudaGetSymbolAddress((void**)&pt2l, g_t2l);
    cudaGetSymbolAddress((void**)&pxch, g_xcath); cudaGetSymbolAddress((void**)&pxcl, g_xcatl);
    cudaGetSymbolAddress((void**)&poah, g_oah); cudaGetSymbolAddress((void**)&poal, g_oal);
    cudaGetSymbolAddress((void**)&po1h, g_o1h); cudaGetSymbolAddress((void**)&po1l, g_o1l);
    cudaGetSymbolAddress((void**)&phh, g_hidh); cudaGetSymbolAddress((void**)&phl, g_hidl);
    cudaGetSymbolAddress((void**)&pwqh, g_wqh); cudaGetSymbolAddress((void**)&pwql, g_wql);
    cudaGetSymbolAddress((void**)&powh, g_owh); cudaGetSymbolAddress((void**)&powl, g_owl);
    cudaGetSymbolAddress((void**)&pw1h, g_w1h); cudaGetSymbolAddress((void**)&pw1l, g_w1l);
    cudaGetSymbolAddress((void**)&pw2h, g_w2h); cudaGetSymbolAddress((void**)&pw2l, g_w2l);
    cudaGetSymbolAddress((void**)&pq, g_q);     cudaGetSymbolAddress((void**)&pk, g_k);
    cudaGetSymbolAddress((void**)&pv, g_v);     cudaGetSymbolAddress((void**)&poproj, g_oproj);
    cudaGetSymbolAddress((void**)&pout1f, g_out1f); cudaGetSymbolAddress((void**)&pffnf, g_ffnf);

    // graph learning
    dim3 gG(NN, 3);
    gk1<<<gG, 256>>>(gl_w1, gl_w2, gl_beta, gl_cw, gl_cb, adj);
    gk2<<<gG, 256>>>();
    gk3<<<gG, 256>>>();
    gk4<<<gG, 256>>>();

    // layout + weight prep
    xsplitT<<<MSP, 192>>>(x);
    pack_x<<<MTOK, 128>>>(x);
    for (int i = 0; i < 3; i++)
        wsplit<<<120, 256>>>(cheb_w + (size_t)i*360*120, pwqh + (size_t)i*128*384,
                             pwql + (size_t)i*128*384, 360, 120, 384);
    wsplit<<<120, 256>>>(out_w, powh, powl, 120, 120, 128);
    wsplit<<<FF, 256>>>(ff_w1, pw1h, pw1l, 120, FF, 128);
    wsplit<<<120, 256>>>(ff_w2, pw2h, pw2l, FF, 120, FF);

    float* qkv[3] = {pq, pk, pv};
    dim3 gsp(MSP/128, 3);   // spatial: BN=64, 3 col tiles -> 192 rows (padded L)
    dim3 gch(MTOK/128, 1);  // channel: BN=128, 1 col tile -> 128 rows (padded W)

    for (int i = 0; i < 3; i++) {
        const __nv_bfloat16* Lih = pLh + (size_t)i*NROWP*NKP;
        const __nv_bfloat16* Lil = pLl + (size_t)i*NROWP*NKP;
        // t1[(bt,d), n] = sum_m xT[(bt,d),m] * L[n,m]
        hmma_bf16x3<64><<<gsp, 256, SMEM64>>>(pxth, pxtl, NKP, Lih, Lil, NKP, NKP,
                                              nullptr, pt1h, pt1l, NKP, NN,
                                              nullptr, 0, nullptr, nullptr);
        // t2 = 2*(L @ t1) - x
        hmma_bf16x3<64><<<gsp, 256, SMEM64>>>(pt1h, pt1l, NKP, Lih, Lil, NKP, NKP,
                                              nullptr, pt2h, pt2l, NKP, NN,
                                              nullptr, FLAG_T2, pxth, pxtl);
        pack12<<<MTOK, 128>>>();
        // qkv_i = relu(xcat @ W_i + b_i), K=384
        hmma_bf16x3<128><<<gch, 256, SMEM128>>>(pxch, pxcl, 384,
                                                pwqh + (size_t)i*128*384, pwql + (size_t)i*128*384,
                                                384, 384,
                                                qkv[i], nullptr, nullptr, DD, DD,
                                                cheb_b + (size_t)i*DD, FLAG_BIAS | FLAG_RELU,
                                                nullptr, nullptr);
    }

    attn_kernel<<<BB*NN, 128>>>(pq, pk, pv);

    // output projection
    hmma_bf16x3<128><<<gch, 256, SMEM128>>>(poah, poal, 128, powh, powl, 128, 128,
                                            poproj, nullptr, nullptr, DD, DD,
                                            out_b, FLAG_BIAS, nullptr, nullptr);
    // LN1: out1 = LN(x + oproj)
    ln_kernel<<<MTOK/4, 128>>>(x, poproj, ln1_g, ln1_b, pout1f, po1h, po1l);

    // FFN1: hidden = relu(out1 @ W1 + b1) -> bf16 h/l
    dim3 gf1(MTOK/128, FF/128);
    hmma_bf16x3<128><<<gf1, 256, SMEM128>>>(po1h, po1l, 128, pw1h, pw1l, 128, 128,
                                            nullptr, phh, phl, FF, FF,
                                            ff_b1, FLAG_BIAS | FLAG_RELU, nullptr, nullptr);
    // FFN2
    hmma_bf16x3<128><<<gch, 256, SMEM128>>>(phh, phl, FF, pw2h, pw2l, FF, FF,
                                            pffnf, nullptr, nullptr, DD, DD,
                                            ff_b2, FLAG_BIAS, nullptr, nullptr);
    // LN2 -> output
    ln_kernel<<<MTOK/4, 128>>>(pout1f, pffnf, ln2_g, ln2_b, outp, nullptr, nullptr);
}

// round 6
// speedup vs baseline: 2.5804x; 1.3029x over previous
#include <cuda_runtime.h>
#include <cuda_bf16.h>
#include <math.h>
#include <stdint.h>

#define NN 170
#define NKP 176            // padded node dim (K of spatial GEMM, multiple of 16)
#define NROWP 192          // padded L rows (3 x 64 col tiles)
#define TT 12
#define BB 32
#define DD 120
#define HH 8
#define HD 15
#define FF 2048
#define BT (BB*TT)          // 384
#define MTOK (BB*TT*NN)     // 65280 = 510*128
#define MSP (BT*DD)         // 46080 = 360*128
#define XK 368              // padded xcat K (360 -> 368)

#define FLAG_BIAS  1
#define FLAG_RELU  2
#define FLAG_T2    4        // epilogue: v = 2*acc - (Xh+Xl)

// ------------------------- static device scratch (zero-initialized) --------
__device__ float g_A[3*NN*NN];
__device__ float g_rs0[3*NN];
__device__ float g_rs1[3*NN];

__device__ __align__(16) __nv_bfloat16 g_Lh[3*NROWP*NKP];
__device__ __align__(16) __nv_bfloat16 g_Ll[3*NROWP*NKP];
__device__ __align__(16) __nv_bfloat16 g_xth[(size_t)MSP*NKP];
__device__ __align__(16) __nv_bfloat16 g_xtl[(size_t)MSP*NKP];
__device__ __align__(16) __nv_bfloat16 g_t1h[(size_t)MSP*NKP];
__device__ __align__(16) __nv_bfloat16 g_t1l[(size_t)MSP*NKP];
__device__ __align__(16) __nv_bfloat16 g_xcath[(size_t)MTOK*XK];
__device__ __align__(16) __nv_bfloat16 g_xcatl[(size_t)MTOK*XK];
__device__ __align__(16) __nv_bfloat16 g_oah[(size_t)MTOK*128];
__device__ __align__(16) __nv_bfloat16 g_oal[(size_t)MTOK*128];
__device__ __align__(16) __nv_bfloat16 g_o1h[(size_t)MTOK*128];
__device__ __align__(16) __nv_bfloat16 g_o1l[(size_t)MTOK*128];
__device__ __align__(16) __nv_bfloat16 g_hidh[(size_t)MTOK*FF];
__device__ __align__(16) __nv_bfloat16 g_hidl[(size_t)MTOK*FF];
// B-operand weights, rows padded to tile boundary
__device__ __align__(16) __nv_bfloat16 g_wqh[3*128*XK];
__device__ __align__(16) __nv_bfloat16 g_wql[3*128*XK];
__device__ __align__(16) __nv_bfloat16 g_owh[128*128];
__device__ __align__(16) __nv_bfloat16 g_owl[128*128];
__device__ __align__(16) __nv_bfloat16 g_w1h[(size_t)FF*128];
__device__ __align__(16) __nv_bfloat16 g_w1l[(size_t)FF*128];
__device__ __align__(16) __nv_bfloat16 g_w2h[(size_t)128*FF];
__device__ __align__(16) __nv_bfloat16 g_w2l[(size_t)128*FF];
__device__ float g_q[(size_t)MTOK*DD];
__device__ float g_k[(size_t)MTOK*DD];
__device__ float g_v[(size_t)MTOK*DD];
__device__ float g_oproj[(size_t)MTOK*DD];
__device__ float g_out1f[(size_t)MTOK*DD];
__device__ float g_ffnf[(size_t)MTOK*DD];

// ------------------------- helpers -------------------------
__device__ __forceinline__ void bsplit(float v, __nv_bfloat16 &h, __nv_bfloat16 &l) {
    h = __float2bfloat16_rn(v);
    l = __float2bfloat16_rn(v - __bfloat162float(h));
}
__device__ __forceinline__ uint32_t smem_u32(const void* p) {
    uint32_t a;
    asm("{ .reg .u64 t; cvta.to.shared.u64 t, %1; cvt.u32.u64 %0, t; }" : "=r"(a) : "l"(p));
    return a;
}
__device__ __forceinline__ void ldm4(uint32_t (&d)[4], uint32_t addr) {
    asm volatile("ldmatrix.sync.aligned.m8n8.x4.shared.b16 {%0,%1,%2,%3}, [%4];"
                 : "=r"(d[0]), "=r"(d[1]), "=r"(d[2]), "=r"(d[3]) : "r"(addr));
}
__device__ __forceinline__ void mma16816(float (&c)[4], const uint32_t (&a)[4],
                                         uint32_t b0, uint32_t b1) {
    asm volatile("mma.sync.aligned.m16n8k16.row.col.f32.bf16.bf16.f32 "
                 "{%0,%1,%2,%3}, {%4,%5,%6,%7}, {%8,%9}, {%0,%1,%2,%3};"
                 : "+f"(c[0]), "+f"(c[1]), "+f"(c[2]), "+f"(c[3])
                 : "r"(a[0]), "r"(a[1]), "r"(a[2]), "r"(a[3]), "r"(b0), "r"(b1));
}

// ------------------------- HMMA bf16x3 GEMM (double-buffered) ---------------
// D[M,N] = sum_k A[m,k]*B[n,k]; A: M x K (lda), B rows padded to tile bound (ldb).
// K%16==0, M%128==0. Outputs:
//   Cf (fp32) or Ch/Cl (bf16 hi/lo) at ldc, cols < Nout
//   optional XCh/XCl: xcat scatter, row gr=(bt*DD+d) -> token (bt*NN+gc), col xoff+d
template<int BN>
__global__ __launch_bounds__(256) void hmma_bf16x3(
        const __nv_bfloat16* __restrict__ Ah, const __nv_bfloat16* __restrict__ Al, int lda,
        const __nv_bfloat16* __restrict__ Bh, const __nv_bfloat16* __restrict__ Bl, int ldb,
        int K,
        float* __restrict__ Cf, __nv_bfloat16* __restrict__ Ch, __nv_bfloat16* __restrict__ Cl,
        int ldc, int Nout,
        const float* __restrict__ bias, int flags,
        const __nv_bfloat16* __restrict__ Xh, const __nv_bfloat16* __restrict__ Xl,
        __nv_bfloat16* __restrict__ XCh, __nv_bfloat16* __restrict__ XCl, int xoff)
{
    constexpr int A16 = 128*3;              // 16B units per A matrix (48B row pitch)
    constexpr int B16 = BN*3;
    constexpr int STAGE_BYTES = (2*A16 + 2*B16) * 16;
    constexpr int NB = (BN*4)/256;
    constexpr int WN = BN / 2;
    constexpr int NP = WN / 16;
    constexpr int BH = BN * 2;

    extern __shared__ __align__(16) char smem[];
    const uint32_t sbase = smem_u32(smem);
    const int tid = threadIdx.x;
    const int lane = tid & 31;
    const int wid = tid >> 5;
    const int wm = wid & 3, wn = wid >> 2;
    const int row0 = blockIdx.x * 128;
    const int col0 = blockIdx.y * BN;

    float acc[2][2*NP][4];
    #pragma unroll
    for (int i = 0; i < 2; i++)
        #pragma unroll
        for (int j = 0; j < 2*NP; j++)
            #pragma unroll
            for (int e = 0; e < 4; e++) acc[i][j][e] = 0.f;

    const int arow = wm*32 + (lane & 15);
    const int akc  = lane >> 4;
    const uint32_t aoff = (uint32_t)(arow*3 + akc) * 16;
    const int brow = wn*WN + (lane & 7) + ((lane >> 4) & 1)*8;
    const int bkc  = (lane >> 3) & 1;
    const uint32_t boff = (uint32_t)(2*A16 + brow*3 + bkc) * 16;

    uint4 ra[2], rb[NB];

    auto gload = [&](int c) {
        const int k0 = c * 16;
        #pragma unroll
        for (int t = 0; t < 2; t++) {
            int i = tid + t*256;
            int mat = i >> 8, u = i & 255, r = u >> 1, kc = u & 1;
            ra[t] = *(const uint4*)((mat ? Al : Ah) + (size_t)(row0 + r)*lda + k0 + kc*8);
        }
        #pragma unroll
        for (int t = 0; t < NB; t++) {
            int i = tid + t*256;
            int mat = i / BH, u = i % BH, r = u >> 1, kc = u & 1;
            rb[t] = *(const uint4*)((mat ? Bl : Bh) + (size_t)(col0 + r)*ldb + k0 + kc*8);
        }
    };
    auto sstore = [&](int st) {
        char* sb = smem + st * STAGE_BYTES;
        #pragma unroll
        for (int t = 0; t < 2; t++) {
            int i = tid + t*256;
            int mat = i >> 8, u = i & 255, r = u >> 1, kc = u & 1;
            *(uint4*)(sb + (uint32_t)(mat*A16 + r*3 + kc)*16) = ra[t];
        }
        #pragma unroll
        for (int t = 0; t < NB; t++) {
            int i = tid + t*256;
            int mat = i / BH, u = i % BH, r = u >> 1, kc = u & 1;
            *(uint4*)(sb + (uint32_t)(2*A16 + mat*B16 + r*3 + kc)*16) = rb[t];
        }
    };

    const int nch = K >> 4;
    gload(0);
    sstore(0);

    for (int c = 0; c < nch; c++) {
        if (c + 1 < nch) gload(c + 1);   // prefetch next chunk into regs
        __syncthreads();                 // stage (c&1) stores visible

        const uint32_t sb = sbase + (uint32_t)(c & 1) * STAGE_BYTES;
        uint32_t ahf[2][4], alf[2][4];
        #pragma unroll
        for (int mi = 0; mi < 2; mi++) {
            uint32_t ad = sb + aoff + (uint32_t)mi * 768;
            ldm4(ahf[mi], ad);
            ldm4(alf[mi], ad + A16*16);
        }
        uint32_t bhf[NP][4], blf[NP][4];
        #pragma unroll
        for (int np = 0; np < NP; np++) {
            uint32_t bd = sb + boff + (uint32_t)np * 768;
            ldm4(bhf[np], bd);
            ldm4(blf[np], bd + B16*16);
        }
        #pragma unroll
        for (int mi = 0; mi < 2; mi++)
            #pragma unroll
            for (int np = 0; np < NP; np++)
                #pragma unroll
                for (int hf = 0; hf < 2; hf++) {
                    int na = np*2 + hf;
                    mma16816(acc[mi][na], ahf[mi], bhf[np][2*hf], bhf[np][2*hf+1]);
                    mma16816(acc[mi][na], ahf[mi], blf[np][2*hf], blf[np][2*hf+1]);
                    mma16816(acc[mi][na], alf[mi], bhf[np][2*hf], bhf[np][2*hf+1]);
                }

        if (c + 1 < nch) sstore((c + 1) & 1);   // opposite stage; safe post-sync
    }

    // ---- epilogue
    float* smemf = (float*)smem;   // reuse stages as BN x 128 fp32 staging (pitch 132)
    if (XCh) __syncthreads();      // all ldmatrix reads of final stage done

    const int lr = lane >> 2, lc = (lane & 3) * 2;
    #pragma unroll
    for (int mi = 0; mi < 2; mi++) {
        #pragma unroll
        for (int na = 0; na < 2*NP; na++) {
            int gr0 = row0 + wm*32 + mi*16 + lr;
            int gc0l = wn*WN + na*8 + lc;       // gc local in [0, BN)
            #pragma unroll
            for (int e = 0; e < 4; e++) {
                int gr = gr0 + (e >> 1) * 8;
                int gcl = gc0l + (e & 1);
                int gc = col0 + gcl;
                if (gc >= Nout) continue;
                float v = acc[mi][na][e];
                size_t ci = (size_t)gr * ldc + gc;
                if (flags & FLAG_T2)
                    v = 2.f*v - (__bfloat162float(Xh[ci]) + __bfloat162float(Xl[ci]));
                if (flags & FLAG_BIAS) v += bias[gc];
                if (flags & FLAG_RELU) v = fmaxf(v, 0.f);
                if (Cf) Cf[ci] = v;
                if (Ch) { __nv_bfloat16 h, l; bsplit(v, h, l); Ch[ci] = h; Cl[ci] = l; }
                if (XCh) smemf[gcl*132 + (gr - row0)] = v;
            }
        }
    }

    if (XCh) {
        __syncthreads();
        for (int i = tid; i < BN*128; i += 256) {
            int gcl = i >> 7, grl = i & 127;
            int n = col0 + gcl;
            if (n >= Nout) continue;
            float v = smemf[gcl*132 + grl];
            int gr = row0 + grl;
            int bt = gr / DD, d = gr - bt*DD;
            __nv_bfloat16 h, l; bsplit(v, h, l);
            size_t idx = ((size_t)bt*NN + n)*XK + xoff + d;
            XCh[idx] = h; XCl[idx] = l;
        }
    }
}

// ------------------------- graph learning -------------------------
__global__ void gk1(const float* __restrict__ w1, const float* __restrict__ w2,
                    const float* __restrict__ beta, const float* __restrict__ cw,
                    const float* __restrict__ cb, const float* __restrict__ adj) {
    int r = blockIdx.x, br = blockIdx.y;
    __shared__ float w1r[DD], w2r[DD];
    __shared__ float red[256];
    const float* W1 = w1 + (size_t)br*NN*DD;
    const float* W2 = w2 + (size_t)br*NN*DD;
    for (int i = threadIdx.x; i < DD; i += blockDim.x) { w1r[i] = W1[r*DD+i]; w2r[i] = W2[r*DD+i]; }
    __syncthreads();
    float cw0 = cw[br*2+0], cw1 = cw[br*2+1], cbv = cb[br];
    float mysum = 0.f;
    for (int c = threadIdx.x; c < NN; c += blockDim.x) {
        const float* w1c = W1 + c*DD;
        const float* w2c = W2 + c*DD;
        float d1 = 0.f, d2 = 0.f;
        for (int e = 0; e < DD; e++) { d1 += w1r[e]*w2c[e]; d2 += w2r[e]*w1c[e]; }
        float nw = d1 - d2;
        if (r == c) nw += beta[br*NN + r];
        nw = fmaxf(nw, 0.f);
        float ad = adj[r*NN + c];
        float gate = 1.f / (1.f + expf(-(cw0*nw + cw1*ad + cbv)));
        float a = gate*nw + (1.f - gate)*ad;
        g_A[(size_t)br*NN*NN + (size_t)r*NN + c] = a;
        mysum += a;
    }
    red[threadIdx.x] = mysum; __syncthreads();
    for (int s = 128; s > 0; s >>= 1) { if (threadIdx.x < s) red[threadIdx.x] += red[threadIdx.x+s]; __syncthreads(); }
    if (threadIdx.x == 0) g_rs0[br*NN + r] = red[0];
}
__global__ void gk2() {
    int r = blockIdx.x, br = blockIdx.y;
    __shared__ float red[256];
    float dr = rsqrtf(g_rs0[br*NN + r]);
    const float eps = 0.5f / (float)NN;
    float mysum = 0.f;
    for (int c = threadIdx.x; c < NN; c += blockDim.x) {
        float dc = rsqrtf(g_rs0[br*NN + c]);
        size_t idx = (size_t)br*NN*NN + (size_t)r*NN + c;
        float a = fmaxf(dr * g_A[idx] * dc - eps, 0.f);
        g_A[idx] = a; mysum += a;
    }
    red[threadIdx.x] = mysum; __syncthreads();
    for (int s = 128; s > 0; s >>= 1) { if (threadIdx.x < s) red[threadIdx.x] += red[threadIdx.x+s]; __syncthreads(); }
    if (threadIdx.x == 0) g_rs1[br*NN + r] = red[0];
}
__global__ void gk3() {
    int r = blockIdx.x, br = blockIdx.y;
    __shared__ float red[256];
    float dr = rsqrtf(g_rs1[br*NN + r]);
    float mysum = 0.f;
    for (int c = threadIdx.x; c < NN; c += blockDim.x) {
        float dc = rsqrtf(g_rs1[br*NN + c]);
        size_t idx = (size_t)br*NN*NN + (size_t)r*NN + c;
        float g = dr * g_A[idx] * dc;
        g_A[idx] = g; mysum += g;
    }
    red[threadIdx.x] = mysum; __syncthreads();
    for (int s = 128; s > 0; s >>= 1) { if (threadIdx.x < s) red[threadIdx.x] += red[threadIdx.x+s]; __syncthreads(); }
    if (threadIdx.x == 0) g_rs0[br*NN + r] = red[0];
}
__global__ void gk4() {
    int r = blockIdx.x, br = blockIdx.y;
    float er = rsqrtf(g_rs0[br*NN + r]);
    for (int c = threadIdx.x; c < NKP; c += blockDim.x) {
        float L = 0.f;
        if (c < NN) {
            float ec = rsqrtf(g_rs0[br*NN + c]);
            L = ((r == c) ? 1.f : 0.f) - er * g_A[(size_t)br*NN*NN + (size_t)r*NN + c] * ec;
        }
        __nv_bfloat16 h, l; bsplit(L, h, l);
        size_t idx = (size_t)br*NROWP*NKP + (size_t)r*NKP + c;
        g_Lh[idx] = h; g_Ll[idx] = l;
    }
}

// ------------------------- layout / split kernels -------------------------
// x (bt,n,d) -> xth/xtl (bt,d | node), coalesced via smem transpose
__global__ void xsplitT(const float* __restrict__ x) {
    __shared__ float s[64*121];
    int bt = blockIdx.x;
    for (int n0 = 0; n0 < NN; n0 += 64) {
        int nrows = (NN - n0 < 64) ? (NN - n0) : 64;
        for (int i = threadIdx.x; i < nrows*DD; i += 256) {
            int nn = i / DD, d = i - nn*DD;
            s[nn*121 + d] = x[((size_t)bt*NN + n0 + nn)*DD + d];
        }
        __syncthreads();
        for (int i = threadIdx.x; i < DD*64; i += 256) {
            int d = i >> 6, nn = i & 63;
            int n = n0 + nn;
            if (nn < nrows) {
                __nv_bfloat16 h, l; bsplit(s[nn*121 + d], h, l);
                size_t idx = ((size_t)bt*DD + d)*NKP + n;
                g_xth[idx] = h; g_xtl[idx] = l;
            }
        }
        __syncthreads();
    }
}
__global__ void pack_x(const float* __restrict__ x) {
    size_t r = blockIdx.x;
    int d = threadIdx.x;
    if (d < DD) {
        __nv_bfloat16 h, l; bsplit(x[r*DD + d], h, l);
        g_xcath[r*XK + d] = h;
        g_xcatl[r*XK + d] = l;
    }
}
__global__ void wsplit(const float* __restrict__ src, __nv_bfloat16* __restrict__ dh,
                       __nv_bfloat16* __restrict__ dl, int K, int N, int ldk) {
    int n = blockIdx.x;
    for (int k = threadIdx.x; k < K; k += blockDim.x) {
        __nv_bfloat16 h, l; bsplit(src[(size_t)k*N + n], h, l);
        dh[(size_t)n*ldk + k] = h;
        dl[(size_t)n*ldk + k] = l;
    }
}

// ------------------------- attention -------------------------
__global__ void attn_kernel(const float* __restrict__ q, const float* __restrict__ k,
                            const float* __restrict__ v) {
    int bn = blockIdx.x;
    int b = bn / NN, n = bn % NN;
    __shared__ float qs[TT][DD], ks[TT][DD], vs[TT][DD];
    for (int i = threadIdx.x; i < TT*DD; i += blockDim.x) {
        int t = i / DD, d = i % DD;
        size_t gi = (((size_t)(b*TT + t))*NN + n)*DD + d;
        qs[t][d] = q[gi]; ks[t][d] = k[gi]; vs[t][d] = v[gi];
    }
    __syncthreads();
    int tid = threadIdx.x;
    if (tid < HH*TT) {
        int h = tid / TT, qi = tid % TT;
        const float scale = rsqrtf((float)HD);
        float s[TT]; float mx = -1e30f;
        #pragma unroll
        for (int j = 0; j < TT; j++) {
            float acc = 0.f;
            #pragma unroll
            for (int e = 0; e < HD; e++) acc += qs[qi][h*HD+e] * ks[j][h*HD+e];
            acc *= scale; s[j] = acc; mx = fmaxf(mx, acc);
        }
        float sum = 0.f;
        #pragma unroll
        for (int j = 0; j < TT; j++) { s[j] = expf(s[j]-mx); sum += s[j]; }
        float inv = 1.f / sum;
        size_t orow = ((size_t)(b*TT + qi))*NN + n;
        #pragma unroll
        for (int e = 0; e < HD; e++) {
            float acc = 0.f;
            #pragma unroll
            for (int j = 0; j < TT; j++) acc += s[j] * vs[j][h*HD+e];
            __nv_bfloat16 hh, ll; bsplit(acc*inv, hh, ll);
            g_oah[orow*128 + h*HD + e] = hh;
            g_oal[orow*128 + h*HD + e] = ll;
        }
    }
}

// ------------------------- residual + layernorm -------------------------
__global__ void ln_kernel(const float* __restrict__ xa, const float* __restrict__ xb,
                          const float* __restrict__ gg, const float* __restrict__ bb,
                          float* __restrict__ outp, __nv_bfloat16* __restrict__ oh,
                          __nv_bfloat16* __restrict__ ol) {
    int warp = threadIdx.x >> 5, lane = threadIdx.x & 31;
    size_t m = (size_t)blockIdx.x * 4 + warp;
    if (m >= MTOK) return;
    size_t ia = m * DD;
    float v[4]; float s = 0.f;
    #pragma unroll
    for (int i = 0; i < 4; i++) {
        int d = lane + 32*i;
        float val = (d < DD) ? (xa[ia+d] + xb[ia+d]) : 0.f;
        v[i] = val; s += val;
    }
    #pragma unroll
    for (int o = 16; o > 0; o >>= 1) s += __shfl_xor_sync(0xffffffffu, s, o);
    float mean = s * (1.f / DD);
    float vsum = 0.f;
    #pragma unroll
    for (int i = 0; i < 4; i++) {
        int d = lane + 32*i;
        if (d < DD) { float df = v[i]-mean; vsum += df*df; }
    }
    #pragma unroll
    for (int o = 16; o > 0; o >>= 1) vsum += __shfl_xor_sync(0xffffffffu, vsum, o);
    float inv = rsqrtf(vsum * (1.f / DD) + 1e-5f);
    #pragma unroll
    for (int i = 0; i < 4; i++) {
        int d = lane + 32*i;
        if (d < DD) {
            float o = (v[i]-mean)*inv*gg[d] + bb[d];
            if (outp) outp[ia + d] = o;
            if (oh) { __nv_bfloat16 h, l; bsplit(o, h, l); oh[m*128 + d] = h; ol[m*128 + d] = l; }
        }
    }
}

// ------------------------- launch -------------------------
extern "C" void kernel_launch(void* const* d_in, const int* in_sizes, int n_in,
                              void* d_out, int out_size) {
    const float* x       = (const float*)d_in[0];
    const float* adj     = (const float*)d_in[1];
    const float* gl_beta = (const float*)d_in[2];
    const float* gl_w1   = (const float*)d_in[3];
    const float* gl_w2   = (const float*)d_in[4];
    const float* gl_cw   = (const float*)d_in[5];
    const float* gl_cb   = (const float*)d_in[6];
    const float* cheb_w  = (const float*)d_in[7];
    const float* cheb_b  = (const float*)d_in[8];
    const float* out_w   = (const float*)d_in[9];
    const float* out_b   = (const float*)d_in[10];
    const float* ff_w1   = (const float*)d_in[11];
    const float* ff_b1   = (const float*)d_in[12];
    const float* ff_w2   = (const float*)d_in[13];
    const float* ff_b2   = (const float*)d_in[14];
    const float* ln1_g   = (const float*)d_in[15];
    const float* ln1_b   = (const float*)d_in[16];
    const float* ln2_g   = (const float*)d_in[17];
    const float* ln2_b   = (const float*)d_in[18];
    float* outp = (float*)d_out;

    const int SMEM128 = 2 * (2*(128*3) + 2*(128*3)) * 16;   // 49152
    const int SMEM64  = 2 * (2*(128*3) + 2*(64*3)) * 16;    // 36864

    __nv_bfloat16 *pLh, *pLl, *pxth, *pxtl, *pt1h, *pt1l;
    __nv_bfloat16 *pxch, *pxcl, *poah, *poal, *po1h, *po1l, *phh, *phl;
    __nv_bfloat16 *pwqh, *pwql, *powh, *powl, *pw1h, *pw1l, *pw2h, *pw2l;
    float *pq, *pk, *pv, *poproj, *pout1f, *pffnf;
    cudaGetSymbolAddress((void**)&pLh, g_Lh);   cudaGetSymbolAddress((void**)&pLl, g_Ll);
    cudaGetSymbolAddress((void**)&pxth, g_xth); cudaGetSymbolAddress((void**)&pxtl, g_xtl);
    cudaGetSymbolAddress((void**)&pt1h, g_t1h); cudaGetSymbolAddress((void**)&pt1l, g_t1l);
    cudaGetSymbolAddress((void**)&pxch, g_xcath); cudaGetSymbolAddress((void**)&pxcl, g_xcatl);
    cudaGetSymbolAddress((void**)&poah, g_oah); cudaGetSymbolAddress((void**)&poal, g_oal);
    cudaGetSymbolAddress((void**)&po1h, g_o1h); cudaGetSymbolAddress((void**)&po1l, g_o1l);
    cudaGetSymbolAddress((void**)&phh, g_hidh); cudaGetSymbolAddress((void**)&phl, g_hidl);
    cudaGetSymbolAddress((void**)&pwqh, g_wqh); cudaGetSymbolAddress((void**)&pwql, g_wql);
    cudaGetSymbolAddress((void**)&powh, g_owh); cudaGetSymbolAddress((void**)&powl, g_owl);
    cudaGetSymbolAddress((void**)&pw1h, g_w1h); cudaGetSymbolAddress((void**)&pw1l, g_w1l);
    cudaGetSymbolAddress((void**)&pw2h, g_w2h); cudaGetSymbolAddress((void**)&pw2l, g_w2l);
    cudaGetSymbolAddress((void**)&pq, g_q);     cudaGetSymbolAddress((void**)&pk, g_k);
    cudaGetSymbolAddress((void**)&pv, g_v);     cudaGetSymbolAddress((void**)&poproj, g_oproj);
    cudaGetSymbolAddress((void**)&pout1f, g_out1f); cudaGetSymbolAddress((void**)&pffnf, g_ffnf);

    // graph learning
    dim3 gG(NN, 3);
    gk1<<<gG, 256>>>(gl_w1, gl_w2, gl_beta, gl_cw, gl_cb, adj);
    gk2<<<gG, 256>>>();
    gk3<<<gG, 256>>>();
    gk4<<<gG, 256>>>();

    // layout + weight prep
    xsplitT<<<BT, 256>>>(x);
    pack_x<<<MTOK, 128>>>(x);
    for (int i = 0; i < 3; i++)
        wsplit<<<120, 256>>>(cheb_w + (size_t)i*360*120, pwqh + (size_t)i*128*XK,
                             pwql + (size_t)i*128*XK, 360, 120, XK);
    wsplit<<<120, 256>>>(out_w, powh, powl, 120, 120, 128);
    wsplit<<<FF, 256>>>(ff_w1, pw1h, pw1l, 120, FF, 128);
    wsplit<<<120, 256>>>(ff_w2, pw2h, pw2l, FF, 120, FF);

    float* qkv[3] = {pq, pk, pv};
    dim3 gsp(MSP/128, 3);   // spatial: BN=64, 3 col tiles (L rows padded to 192)
    dim3 gch(MTOK/128, 1);  // channel: BN=128

    for (int i = 0; i < 3; i++) {
        const __nv_bfloat16* Lih = pLh + (size_t)i*NROWP*NKP;
        const __nv_bfloat16* Lil = pLl + (size_t)i*NROWP*NKP;
        // t1 = L @ x : write t-layout (for T2 chain) + xcat[120..239]
        hmma_bf16x3<64><<<gsp, 256, SMEM64>>>(pxth, pxtl, NKP, Lih, Lil, NKP, NKP,
                                              nullptr, pt1h, pt1l, NKP, NN,
                                              nullptr, 0, nullptr, nullptr,
                                              pxch, pxcl, 120);
        // t2 = 2*(L @ t1) - x : write xcat[240..359] only
        hmma_bf16x3<64><<<gsp, 256, SMEM64>>>(pt1h, pt1l, NKP, Lih, Lil, NKP, NKP,
                                              nullptr, nullptr, nullptr, NKP, NN,
                                              nullptr, FLAG_T2, pxth, pxtl,
                                              pxch, pxcl, 240);
        // qkv_i = relu(xcat @ W_i + b_i), K=368
        hmma_bf16x3<128><<<gch, 256, SMEM128>>>(pxch, pxcl, XK,
                                                pwqh + (size_t)i*128*XK, pwql + (size_t)i*128*XK,
                                                XK, XK,
                                                qkv[i], nullptr, nullptr, DD, DD,
                                                cheb_b + (size_t)i*DD, FLAG_BIAS | FLAG_RELU,
                                                nullptr, nullptr, nullptr, nullptr, 0);
    }

    attn_kernel<<<BB*NN, 128>>>(pq, pk, pv);

    // output projection
    hmma_bf16x3<128><<<gch, 256, SMEM128>>>(poah, poal, 128, powh, powl, 128, 128,
                                            poproj, nullptr, nullptr, DD, DD,
                                            out_b, FLAG_BIAS, nullptr, nullptr,
                                            nullptr, nullptr, 0);
    // LN1: out1 = LN(x + oproj)
    ln_kernel<<<MTOK/4, 128>>>(x, poproj, ln1_g, ln1_b, pout1f, po1h, po1l);

    // FFN1: hidden = relu(out1 @ W1 + b1) -> bf16 h/l
    dim3 gf1(MTOK/128, FF/128);
    hmma_bf16x3<128><<<gf1, 256, SMEM128>>>(po1h, po1l, 128, pw1h, pw1l, 128, 128,
                                            nullptr, phh, phl, FF, FF,
                                            ff_b1, FLAG_BIAS | FLAG_RELU, nullptr, nullptr,
                                            nullptr, nullptr, 0);
    // FFN2
    hmma_bf16x3<128><<<gch, 256, SMEM128>>>(phh, phl, FF, pw2h, pw2l, FF, FF,
                                            pffnf, nullptr, nullptr, DD, DD,
                                            ff_b2, FLAG_BIAS, nullptr, nullptr,
                                            nullptr, nullptr, 0);
    // LN2 -> output
    ln_kernel<<<MTOK/4, 128>>>(pout1f, pffnf, ln2_g, ln2_b, outp, nullptr, nullptr);
}